// round 8
// baseline (speedup 1.0000x reference)
#include <cuda_runtime.h>
#include <cstdint>

#define BB 32768
#define IN 512
#define HID 256
#define OUT 128
#define NE 16
#define CTX 256
#define DEMO 16
#define GATE_IN 784

// ---------------- device scratch (allocation-free) ----------------
__device__ float g_xr[BB * IN];          // tf32-rounded x (written by gate_k)
__device__ float g_W1r[NE * HID * IN];   // tf32-rounded W1
__device__ float g_W2r[NE * OUT * HID];  // tf32-rounded W2
__device__ float g_wgt[BB * NE];         // softmax gate weights

// ---------------- helpers ----------------
__device__ __forceinline__ float frna(float x) {
    uint32_t r;
    asm("cvt.rna.tf32.f32 %0, %1;" : "=r"(r) : "f"(x));
    return __uint_as_float(r);
}
__device__ __forceinline__ void cp16(void* s, const void* g) {
    uint32_t sa = (uint32_t)__cvta_generic_to_shared(s);
    asm volatile("cp.async.cg.shared.global [%0], [%1], 16;" :: "r"(sa), "l"(g));
}
__device__ __forceinline__ void cp_commit() { asm volatile("cp.async.commit_group;"); }
__device__ __forceinline__ void cp_wait0()  { asm volatile("cp.async.wait_group 0;" ::: "memory"); }

__device__ __forceinline__ void mma_tf32(float* c, const uint32_t* a,
                                         uint32_t b0, uint32_t b1) {
    asm volatile(
        "mma.sync.aligned.m16n8k8.row.col.f32.tf32.tf32.f32 "
        "{%0,%1,%2,%3},{%4,%5,%6,%7},{%8,%9},{%0,%1,%2,%3};\n"
        : "+f"(c[0]), "+f"(c[1]), "+f"(c[2]), "+f"(c[3])
        : "r"(a[0]), "r"(a[1]), "r"(a[2]), "r"(a[3]), "r"(b0), "r"(b1));
}

// ---------------- gate: logits + softmax + fused x rounding + W rounding ----------------
#define W1_F4 (NE * HID * IN / 4)
#define W2_F4 (NE * OUT * HID / 4)

__device__ __forceinline__ void gfma(float* acc, const float* gWs, int k, float v) {
    const float4* w = (const float4*)(gWs + k * 16);
    #pragma unroll
    for (int q = 0; q < 4; ++q) {
        float4 ww = w[q];
        acc[q * 4 + 0] += v * ww.x; acc[q * 4 + 1] += v * ww.y;
        acc[q * 4 + 2] += v * ww.z; acc[q * 4 + 3] += v * ww.w;
    }
}

__global__ __launch_bounds__(256) void gate_k(
    const float* __restrict__ u, const float* __restrict__ x,
    const float* __restrict__ d, const float* __restrict__ gW,
    const float* __restrict__ gb,
    const float* __restrict__ W1, const float* __restrict__ W2) {
    extern __shared__ float gWs[];  // [784][16] transposed
    int tid = threadIdx.x;

    // ---- folded W1/W2 tf32 rounding (grid-stride) ----
    {
        int gtid = blockIdx.x * 256 + tid;
        int nthr = gridDim.x * 256;
        for (int i = gtid; i < W1_F4; i += nthr) {
            float4 v = ((const float4*)W1)[i];
            ((float4*)g_W1r)[i] = make_float4(frna(v.x), frna(v.y), frna(v.z), frna(v.w));
        }
        for (int i = gtid; i < W2_F4; i += nthr) {
            float4 v = ((const float4*)W2)[i];
            ((float4*)g_W2r)[i] = make_float4(frna(v.x), frna(v.y), frna(v.z), frna(v.w));
        }
    }

    for (int i = tid; i < GATE_IN * NE; i += 256) {
        int e = i / GATE_IN, k = i - e * GATE_IN;
        gWs[k * 16 + e] = gW[i];
    }
    __syncthreads();

    int r = blockIdx.x * 256 + tid;
    float acc[16];
    #pragma unroll
    for (int e = 0; e < 16; ++e) acc[e] = gb[e];

    const float4* u4 = (const float4*)(u + (size_t)r * CTX);
    const float4* x4 = (const float4*)(x + (size_t)r * IN);
    const float4* d4 = (const float4*)(d + (size_t)r * DEMO);
    float4* xr4 = (float4*)(g_xr + (size_t)r * IN);

    int kb = 0;
    #pragma unroll 4
    for (int i = 0; i < CTX / 4; ++i) {
        float4 v = u4[i];
        gfma(acc, gWs, kb + 0, v.x); gfma(acc, gWs, kb + 1, v.y);
        gfma(acc, gWs, kb + 2, v.z); gfma(acc, gWs, kb + 3, v.w);
        kb += 4;
    }
    #pragma unroll 4
    for (int i = 0; i < IN / 4; ++i) {
        float4 v = x4[i];
        gfma(acc, gWs, kb + 0, v.x); gfma(acc, gWs, kb + 1, v.y);
        gfma(acc, gWs, kb + 2, v.z); gfma(acc, gWs, kb + 3, v.w);
        kb += 4;
        xr4[i] = make_float4(frna(v.x), frna(v.y), frna(v.z), frna(v.w));
    }
    #pragma unroll
    for (int i = 0; i < DEMO / 4; ++i) {
        float4 v = d4[i];
        gfma(acc, gWs, kb + 0, v.x); gfma(acc, gWs, kb + 1, v.y);
        gfma(acc, gWs, kb + 2, v.z); gfma(acc, gWs, kb + 3, v.w);
        kb += 4;
    }

    float m = acc[0];
    #pragma unroll
    for (int e = 1; e < 16; ++e) m = fmaxf(m, acc[e]);
    float s = 0.f;
    #pragma unroll
    for (int e = 0; e < 16; ++e) { acc[e] = expf(acc[e] - m); s += acc[e]; }
    float inv = 1.f / s;
    #pragma unroll
    for (int e = 0; e < 16; ++e) g_wgt[(size_t)r * NE + e] = acc[e] * inv;
}

// ---------------- main fused MoE kernel (mma.sync tf32, 512 threads) ----------------
// SMEM float layout (44544 floats = 178176 B):
//   [0, 33280)        Hs  : 128 x 260 (phase-A staging Xs/Ws aliases here)
//     alias: Xs 2 x (128*36)=9216 at 0 ; Ws 2 x (256*36)=18432 at 9216
//   [33280, 42496)    W2s : 2 x (128*36)
//   [42496, 44544)    wts : 128 x 16 gate weights
#define HS_STRIDE 260
#define XS_OFF    0
#define WS_OFF    9216
#define W2S_OFF   33280
#define WTS_OFF   42496
#define SMEM_BYTES (44544 * 4)
#define NTHR 512

__device__ __forceinline__ void stageA(float* sm, int tid, int b0, int e, int ci, int buf) {
    float* xs = sm + XS_OFF + buf * 4608;
    float* ws = sm + WS_OFF + buf * 9216;
    const float* xsrc = g_xr + (size_t)b0 * IN + ci * 32;
    const float* wsrc = g_W1r + (size_t)e * HID * IN + ci * 32;
    #pragma unroll
    for (int j = 0; j < 2; ++j) {               // X chunk: 128 x 32 (1024 cp16)
        int v = tid + j * NTHR;
        int r = v >> 3, c = (v & 7) * 4;
        cp16(xs + r * 36 + c, xsrc + (size_t)r * IN + c);
    }
    #pragma unroll
    for (int j = 0; j < 4; ++j) {               // W1 chunk: 256 x 32 (2048 cp16)
        int v = tid + j * NTHR;
        int n = v >> 3, c = (v & 7) * 4;
        cp16(ws + n * 36 + c, wsrc + (size_t)n * IN + c);
    }
}
__device__ __forceinline__ void stageB(float* sm, int tid, int e, int ci, int buf) {
    float* w2 = sm + W2S_OFF + buf * 4608;
    const float* src = g_W2r + (size_t)e * OUT * HID + ci * 32;
    #pragma unroll
    for (int j = 0; j < 2; ++j) {               // W2 chunk: 128 x 32 (1024 cp16)
        int v = tid + j * NTHR;
        int o = v >> 3, c = (v & 7) * 4;
        cp16(w2 + o * 36 + c, src + (size_t)o * HID + c);
    }
}

__global__ __launch_bounds__(NTHR, 1) void moe_main(
    const float* __restrict__ b1, const float* __restrict__ b2,
    float* __restrict__ out) {
    extern __shared__ float sm[];
    const int tid  = threadIdx.x;
    const int warp = tid >> 5, lane = tid & 31;
    const int g = lane >> 2, t = lane & 3;
    const int b0 = blockIdx.x * 128;

    float* Hs  = sm;
    float* wts = sm + WTS_OFF;

    for (int i = tid; i < 128 * NE; i += NTHR) wts[i] = g_wgt[(size_t)b0 * NE + i];

    // warp tiling: 4 (M) x 4 (N) warps
    const int wm  = (warp & 3) * 32;   // row base (both phases)
    const int wn1 = (warp >> 2) * 64;  // phase-A col base (HID=256)
    const int wn2 = (warp >> 2) * 32;  // phase-B col base (OUT=128)

    float acc2[2][4][4];               // persistent mixture accumulator
    #pragma unroll
    for (int a = 0; a < 2; ++a)
        #pragma unroll
        for (int b = 0; b < 4; ++b)
            #pragma unroll
            for (int c = 0; c < 4; ++c) acc2[a][b][c] = 0.f;

    __syncthreads();

    for (int e = 0; e < NE; ++e) {
        // ===== Phase A: H = relu(X @ W1_e^T + b1) * w  (K=512, 16 chunks) =====
        float acc1[2][8][4];
        #pragma unroll
        for (int a = 0; a < 2; ++a)
            #pragma unroll
            for (int b = 0; b < 8; ++b)
                #pragma unroll
                for (int c = 0; c < 4; ++c) acc1[a][b][c] = 0.f;

        stageA(sm, tid, b0, e, 0, 0);
        cp_commit();

        for (int ci = 0; ci < 16; ++ci) {
            int cur = ci & 1;
            cp_wait0(); __syncthreads();                    // buffer[cur] ready
            if (ci < 15) { stageA(sm, tid, b0, e, ci + 1, cur ^ 1); cp_commit(); }
            const uint32_t* xp = (const uint32_t*)(sm + XS_OFF + cur * 4608);
            const uint32_t* wp = (const uint32_t*)(sm + WS_OFF + cur * 9216);
            #pragma unroll
            for (int kki = 0; kki < 4; ++kki) {
                const int kk = kki * 8;
                uint32_t a[2][4];
                #pragma unroll
                for (int mf = 0; mf < 2; ++mf) {
                    int r = wm + mf * 16 + g;
                    a[mf][0] = xp[r * 36 + kk + t];
                    a[mf][1] = xp[(r + 8) * 36 + kk + t];
                    a[mf][2] = xp[r * 36 + kk + t + 4];
                    a[mf][3] = xp[(r + 8) * 36 + kk + t + 4];
                }
                #pragma unroll
                for (int nf = 0; nf < 8; ++nf) {
                    int n = wn1 + nf * 8 + g;
                    uint32_t bb0 = wp[n * 36 + kk + t];
                    uint32_t bb1 = wp[n * 36 + kk + t + 4];
                    #pragma unroll
                    for (int mf = 0; mf < 2; ++mf)
                        mma_tf32(acc1[mf][nf], a[mf], bb0, bb1);
                }
            }
            __syncthreads();   // all warps done reading buffer[cur] before re-stage
        }

        // prefetch W2 chunk0 (separate region; overlaps epilogue)
        stageB(sm, tid, e, 0, 0);
        cp_commit();

        // epilogue A: relu + bias + gate-weight scale, tf32-round, store H
        #pragma unroll
        for (int mf = 0; mf < 2; ++mf) {
            int r0 = wm + mf * 16 + g, r1 = r0 + 8;
            float w0 = wts[r0 * NE + e], w1 = wts[r1 * NE + e];
            #pragma unroll
            for (int nf = 0; nf < 8; ++nf) {
                int c0 = wn1 + nf * 8 + 2 * t;
                float bb0 = b1[e * HID + c0], bb1 = b1[e * HID + c0 + 1];
                Hs[r0 * HS_STRIDE + c0]     = frna(fmaxf(acc1[mf][nf][0] + bb0, 0.f) * w0);
                Hs[r0 * HS_STRIDE + c0 + 1] = frna(fmaxf(acc1[mf][nf][1] + bb1, 0.f) * w0);
                Hs[r1 * HS_STRIDE + c0]     = frna(fmaxf(acc1[mf][nf][2] + bb0, 0.f) * w1);
                Hs[r1 * HS_STRIDE + c0 + 1] = frna(fmaxf(acc1[mf][nf][3] + bb1, 0.f) * w1);
            }
        }

        // ===== Phase B: out += (w*H_e) @ W2_e^T  (K=256, 8 chunks) =====
        const uint32_t* Hp = (const uint32_t*)Hs;
        for (int ci = 0; ci < 8; ++ci) {
            int cur = ci & 1;
            cp_wait0(); __syncthreads();   // W2[cur] ready; ci==0 also orders H stores
            if (ci < 7) { stageB(sm, tid, e, ci + 1, cur ^ 1); cp_commit(); }
            const uint32_t* w2p = (const uint32_t*)(sm + W2S_OFF + cur * 4608);
            #pragma unroll
            for (int kki = 0; kki < 4; ++kki) {
                const int kk = kki * 8;
                const int kc = ci * 32 + kk;
                uint32_t a[2][4];
                #pragma unroll
                for (int mf = 0; mf < 2; ++mf) {
                    int r = wm + mf * 16 + g;
                    a[mf][0] = Hp[r * HS_STRIDE + kc + t];
                    a[mf][1] = Hp[(r + 8) * HS_STRIDE + kc + t];
                    a[mf][2] = Hp[r * HS_STRIDE + kc + t + 4];
                    a[mf][3] = Hp[(r + 8) * HS_STRIDE + kc + t + 4];
                }
                #pragma unroll
                for (int nf = 0; nf < 4; ++nf) {
                    int n = wn2 + nf * 8 + g;
                    uint32_t bb0 = w2p[n * 36 + kk + t];
                    uint32_t bb1 = w2p[n * 36 + kk + t + 4];
                    #pragma unroll
                    for (int mf = 0; mf < 2; ++mf)
                        mma_tf32(acc2[mf][nf], a[mf], bb0, bb1);
                }
            }
            __syncthreads();
        }
        // all warps done reading Hs; next expert's stageA may overwrite it
    }

    // ===== epilogue: out = acc2 + sum_e w[b,e] * b2[e,:] =====
    #pragma unroll
    for (int mf = 0; mf < 2; ++mf) {
        int r0 = wm + mf * 16 + g, r1 = r0 + 8;
        #pragma unroll
        for (int nf = 0; nf < 4; ++nf) {
            int c0 = wn2 + nf * 8 + 2 * t;
            float s0 = acc2[mf][nf][0], s1 = acc2[mf][nf][1];
            float s2 = acc2[mf][nf][2], s3 = acc2[mf][nf][3];
            #pragma unroll
            for (int e = 0; e < NE; ++e) {
                float bb0 = b2[e * OUT + c0], bb1 = b2[e * OUT + c0 + 1];
                float we0 = wts[r0 * NE + e], we1 = wts[r1 * NE + e];
                s0 += we0 * bb0; s1 += we0 * bb1;
                s2 += we1 * bb0; s3 += we1 * bb1;
            }
            out[(size_t)(b0 + r0) * OUT + c0]     = s0;
            out[(size_t)(b0 + r0) * OUT + c0 + 1] = s1;
            out[(size_t)(b0 + r1) * OUT + c0]     = s2;
            out[(size_t)(b0 + r1) * OUT + c0 + 1] = s3;
        }
    }
}

// ---------------- launch (2 kernels) ----------------
extern "C" void kernel_launch(void* const* d_in, const int* in_sizes, int n_in,
                              void* d_out, int out_size) {
    const float* x  = (const float*)d_in[0];
    const float* u  = (const float*)d_in[1];
    const float* dd = (const float*)d_in[2];
    const float* gW = (const float*)d_in[3];
    const float* gb = (const float*)d_in[4];
    const float* W1 = (const float*)d_in[5];
    const float* b1 = (const float*)d_in[6];
    const float* W2 = (const float*)d_in[7];
    const float* b2 = (const float*)d_in[8];
    float* out = (float*)d_out;

    cudaFuncSetAttribute(gate_k, cudaFuncAttributeMaxDynamicSharedMemorySize,
                         GATE_IN * NE * 4);
    cudaFuncSetAttribute(moe_main, cudaFuncAttributeMaxDynamicSharedMemorySize,
                         SMEM_BYTES);

    gate_k<<<BB / 256, 256, GATE_IN * NE * 4>>>(u, x, dd, gW, gb, W1, W2);
    moe_main<<<BB / 128, NTHR, SMEM_BYTES>>>(b1, b2, out);
}

// round 9
// speedup vs baseline: 1.6053x; 1.6053x over previous
#include <cuda_runtime.h>
#include <cuda_fp16.h>
#include <cstdint>

#define BB 32768
#define IN 512
#define HID 256
#define OUT 128
#define NE 16
#define CTX 256
#define DEMO 16
#define GATE_IN 784

// ---------------- device scratch: fp16 pairs packed in u32 along K ----------------
__device__ uint32_t g_xh[BB * IN / 2];           // x  as fp16x2
__device__ uint32_t g_w1h[NE * HID * IN / 2];    // W1 as fp16x2
__device__ uint32_t g_w2h[NE * OUT * HID / 2];   // W2 as fp16x2
__device__ float    g_wgt[BB * NE];              // softmax gate weights

// ---------------- helpers ----------------
__device__ __forceinline__ uint32_t pack_h2(float a, float b) {
    __half2 h = __floats2half2_rn(a, b);
    return *(uint32_t*)&h;
}
__device__ __forceinline__ void cp16(void* s, const void* g) {
    uint32_t sa = (uint32_t)__cvta_generic_to_shared(s);
    asm volatile("cp.async.cg.shared.global [%0], [%1], 16;" :: "r"(sa), "l"(g));
}
__device__ __forceinline__ void cp_commit() { asm volatile("cp.async.commit_group;"); }
__device__ __forceinline__ void cp_wait0()  { asm volatile("cp.async.wait_group 0;" ::: "memory"); }

__device__ __forceinline__ void mma_f16(float* c, const uint32_t* a,
                                        uint32_t b0, uint32_t b1) {
    asm volatile(
        "mma.sync.aligned.m16n8k16.row.col.f32.f16.f16.f32 "
        "{%0,%1,%2,%3},{%4,%5,%6,%7},{%8,%9},{%0,%1,%2,%3};\n"
        : "+f"(c[0]), "+f"(c[1]), "+f"(c[2]), "+f"(c[3])
        : "r"(a[0]), "r"(a[1]), "r"(a[2]), "r"(a[3]), "r"(b0), "r"(b1));
}

// ---------------- gate: logits + softmax + fused x/W fp16 conversion ----------------
#define W1_F4 (NE * HID * IN / 4)
#define W2_F4 (NE * OUT * HID / 4)

__device__ __forceinline__ void gfma(float* acc, const float* gWs, int k, float v) {
    const float4* w = (const float4*)(gWs + k * 16);
    #pragma unroll
    for (int q = 0; q < 4; ++q) {
        float4 ww = w[q];
        acc[q * 4 + 0] += v * ww.x; acc[q * 4 + 1] += v * ww.y;
        acc[q * 4 + 2] += v * ww.z; acc[q * 4 + 3] += v * ww.w;
    }
}

__global__ __launch_bounds__(256) void gate_k(
    const float* __restrict__ u, const float* __restrict__ x,
    const float* __restrict__ d, const float* __restrict__ gW,
    const float* __restrict__ gb,
    const float* __restrict__ W1, const float* __restrict__ W2) {
    extern __shared__ float gWs[];  // [784][16] transposed
    int tid = threadIdx.x;

    // ---- folded W1/W2 fp16 conversion (grid-stride) ----
    {
        int gtid = blockIdx.x * 256 + tid;
        int nthr = gridDim.x * 256;
        for (int i = gtid; i < W1_F4; i += nthr) {
            float4 v = ((const float4*)W1)[i];
            g_w1h[2 * i]     = pack_h2(v.x, v.y);
            g_w1h[2 * i + 1] = pack_h2(v.z, v.w);
        }
        for (int i = gtid; i < W2_F4; i += nthr) {
            float4 v = ((const float4*)W2)[i];
            g_w2h[2 * i]     = pack_h2(v.x, v.y);
            g_w2h[2 * i + 1] = pack_h2(v.z, v.w);
        }
    }

    for (int i = tid; i < GATE_IN * NE; i += 256) {
        int e = i / GATE_IN, k = i - e * GATE_IN;
        gWs[k * 16 + e] = gW[i];
    }
    __syncthreads();

    int r = blockIdx.x * 256 + tid;
    float acc[16];
    #pragma unroll
    for (int e = 0; e < 16; ++e) acc[e] = gb[e];

    const float4* u4 = (const float4*)(u + (size_t)r * CTX);
    const float4* x4 = (const float4*)(x + (size_t)r * IN);
    const float4* d4 = (const float4*)(d + (size_t)r * DEMO);

    int kb = 0;
    #pragma unroll 4
    for (int i = 0; i < CTX / 4; ++i) {
        float4 v = u4[i];
        gfma(acc, gWs, kb + 0, v.x); gfma(acc, gWs, kb + 1, v.y);
        gfma(acc, gWs, kb + 2, v.z); gfma(acc, gWs, kb + 3, v.w);
        kb += 4;
    }
    #pragma unroll 4
    for (int i = 0; i < IN / 4; ++i) {
        float4 v = x4[i];
        gfma(acc, gWs, kb + 0, v.x); gfma(acc, gWs, kb + 1, v.y);
        gfma(acc, gWs, kb + 2, v.z); gfma(acc, gWs, kb + 3, v.w);
        kb += 4;
        size_t bidx = (size_t)r * (IN / 2) + 2 * i;
        g_xh[bidx]     = pack_h2(v.x, v.y);
        g_xh[bidx + 1] = pack_h2(v.z, v.w);
    }
    #pragma unroll
    for (int i = 0; i < DEMO / 4; ++i) {
        float4 v = d4[i];
        gfma(acc, gWs, kb + 0, v.x); gfma(acc, gWs, kb + 1, v.y);
        gfma(acc, gWs, kb + 2, v.z); gfma(acc, gWs, kb + 3, v.w);
        kb += 4;
    }

    float m = acc[0];
    #pragma unroll
    for (int e = 1; e < 16; ++e) m = fmaxf(m, acc[e]);
    float s = 0.f;
    #pragma unroll
    for (int e = 0; e < 16; ++e) { acc[e] = expf(acc[e] - m); s += acc[e]; }
    float inv = 1.f / s;
    #pragma unroll
    for (int e = 0; e < 16; ++e) g_wgt[(size_t)r * NE + e] = acc[e] * inv;
}

// ---------------- main fused MoE kernel (fp16 m16n8k16 mma.sync, R5 pipeline) ----------------
// SMEM u32 layout (24064 u32 = 96256 B):
//   [0, 16896)    Hs : 128 x 132 fp16-pair tile (phase-A staging aliases here)
//     alias: XA 2 x (128*20)=5120 at 0 ; WA 2 x (256*20)=10240 at 5120
//   [16896, 22016) W2 staging: 2 x (128*20)
//   [22016, 24064) wts (float) 128 x 16
#define HS_STRIDE 132
#define XA_OFF  0
#define XA_BUF  2560
#define WA_OFF  5120
#define WA_BUF  5120
#define W2_OFF  16896
#define W2_BUF  2560
#define WTS_OFF 22016
#define SMEM_BYTES (24064 * 4)

__device__ __forceinline__ void stageA(uint32_t* sm, int tid, int b0, int e, int ci, int buf) {
    uint32_t* xs = sm + XA_OFF + buf * XA_BUF;
    uint32_t* ws = sm + WA_OFF + buf * WA_BUF;
    const uint32_t* xsrc = g_xh + (size_t)b0 * (IN / 2) + ci * 16;
    const uint32_t* wsrc = g_w1h + (size_t)e * HID * (IN / 2) + ci * 16;
    #pragma unroll
    for (int j = 0; j < 2; ++j) {               // X: 128 rows x 16 u32 (512 cp16)
        int v = tid + j * 256;
        int r = v >> 2, q = (v & 3) * 4;
        cp16(xs + r * 20 + q, xsrc + (size_t)r * (IN / 2) + q);
    }
    #pragma unroll
    for (int j = 0; j < 4; ++j) {               // W1: 256 rows x 16 u32 (1024 cp16)
        int v = tid + j * 256;
        int n = v >> 2, q = (v & 3) * 4;
        cp16(ws + n * 20 + q, wsrc + (size_t)n * (IN / 2) + q);
    }
}
__device__ __forceinline__ void stageB(uint32_t* sm, int tid, int e, int ci, int buf) {
    uint32_t* w2 = sm + W2_OFF + buf * W2_BUF;
    const uint32_t* src = g_w2h + (size_t)e * OUT * (HID / 2) + ci * 16;
    #pragma unroll
    for (int j = 0; j < 2; ++j) {               // W2: 128 rows x 16 u32 (512 cp16)
        int v = tid + j * 256;
        int o = v >> 2, q = (v & 3) * 4;
        cp16(w2 + o * 20 + q, src + (size_t)o * (HID / 2) + q);
    }
}

__global__ __launch_bounds__(256, 1) void moe_main(
    const float* __restrict__ b1, const float* __restrict__ b2,
    float* __restrict__ out) {
    extern __shared__ uint32_t smu[];
    const int tid  = threadIdx.x;
    const int warp = tid >> 5, lane = tid & 31;
    const int g = lane >> 2, t = lane & 3;
    const int b0 = blockIdx.x * 128;

    float* wts = (float*)(smu + WTS_OFF);
    for (int i = tid; i < 128 * NE; i += 256) wts[i] = g_wgt[(size_t)b0 * NE + i];

    // warp tiling: 2 (M) x 4 (N) warps
    const int wm  = (warp & 1) * 64;   // row base (both phases)
    const int wn1 = (warp >> 1) * 64;  // phase-A col base (HID=256)
    const int wn2 = (warp >> 1) * 32;  // phase-B col base (OUT=128)

    float acc2[4][4][4];               // persistent mixture accumulator
    #pragma unroll
    for (int a = 0; a < 4; ++a)
        #pragma unroll
        for (int b = 0; b < 4; ++b)
            #pragma unroll
            for (int c = 0; c < 4; ++c) acc2[a][b][c] = 0.f;

    __syncthreads();

    for (int e = 0; e < NE; ++e) {
        // ===== Phase A: H = relu(X @ W1_e^T + b1) * w  (K=512, 16 chunks of 32) =====
        float acc1[4][8][4];
        #pragma unroll
        for (int a = 0; a < 4; ++a)
            #pragma unroll
            for (int b = 0; b < 8; ++b)
                #pragma unroll
                for (int c = 0; c < 4; ++c) acc1[a][b][c] = 0.f;

        stageA(smu, tid, b0, e, 0, 0);
        cp_commit();

        for (int ci = 0; ci < 16; ++ci) {
            int cur = ci & 1;
            cp_wait0(); __syncthreads();                    // buffer[cur] ready
            if (ci < 15) { stageA(smu, tid, b0, e, ci + 1, cur ^ 1); cp_commit(); }
            const uint32_t* xp = smu + XA_OFF + cur * XA_BUF;
            const uint32_t* wp = smu + WA_OFF + cur * WA_BUF;
            #pragma unroll
            for (int ks = 0; ks < 2; ++ks) {                // two k16 slices per chunk
                const int pb = ks * 8;                      // pair base
                uint32_t a[4][4];
                #pragma unroll
                for (int mf = 0; mf < 4; ++mf) {
                    int r = wm + mf * 16 + g;
                    a[mf][0] = xp[r * 20 + pb + t];
                    a[mf][1] = xp[(r + 8) * 20 + pb + t];
                    a[mf][2] = xp[r * 20 + pb + t + 4];
                    a[mf][3] = xp[(r + 8) * 20 + pb + t + 4];
                }
                #pragma unroll
                for (int nf = 0; nf < 8; ++nf) {
                    int n = wn1 + nf * 8 + g;
                    uint32_t bb0 = wp[n * 20 + pb + t];
                    uint32_t bb1 = wp[n * 20 + pb + t + 4];
                    #pragma unroll
                    for (int mf = 0; mf < 4; ++mf)
                        mma_f16(acc1[mf][nf], a[mf], bb0, bb1);
                }
            }
            __syncthreads();   // all warps done reading buffer[cur] before re-stage
        }

        // prefetch W2 chunk0 (separate region; overlaps epilogue)
        stageB(smu, tid, e, 0, 0);
        cp_commit();

        // epilogue A: relu + bias + gate-weight scale, fp16 pack, store H
        #pragma unroll
        for (int mf = 0; mf < 4; ++mf) {
            int r0 = wm + mf * 16 + g, r1 = r0 + 8;
            float w0 = wts[r0 * NE + e], w1 = wts[r1 * NE + e];
            #pragma unroll
            for (int nf = 0; nf < 8; ++nf) {
                int c0 = wn1 + nf * 8 + 2 * t;
                int p  = c0 >> 1;                           // pair index
                float bb0 = b1[e * HID + c0], bb1 = b1[e * HID + c0 + 1];
                float v00 = fmaxf(acc1[mf][nf][0] + bb0, 0.f) * w0;
                float v01 = fmaxf(acc1[mf][nf][1] + bb1, 0.f) * w0;
                float v10 = fmaxf(acc1[mf][nf][2] + bb0, 0.f) * w1;
                float v11 = fmaxf(acc1[mf][nf][3] + bb1, 0.f) * w1;
                smu[r0 * HS_STRIDE + p] = pack_h2(v00, v01);
                smu[r1 * HS_STRIDE + p] = pack_h2(v10, v11);
            }
        }

        // ===== Phase B: out += (w*H_e) @ W2_e^T  (K=256, 8 chunks of 32) =====
        for (int ci = 0; ci < 8; ++ci) {
            int cur = ci & 1;
            cp_wait0(); __syncthreads();   // W2[cur] ready; ci==0 also orders H stores
            if (ci < 7) { stageB(smu, tid, e, ci + 1, cur ^ 1); cp_commit(); }
            const uint32_t* w2p = smu + W2_OFF + cur * W2_BUF;
            #pragma unroll
            for (int ks = 0; ks < 2; ++ks) {
                const int pb  = ci * 16 + ks * 8;           // pair base into Hs
                const int pb2 = ks * 8;                     // within W2 tile
                uint32_t a[4][4];
                #pragma unroll
                for (int mf = 0; mf < 4; ++mf) {
                    int r = wm + mf * 16 + g;
                    a[mf][0] = smu[r * HS_STRIDE + pb + t];
                    a[mf][1] = smu[(r + 8) * HS_STRIDE + pb + t];
                    a[mf][2] = smu[r * HS_STRIDE + pb + t + 4];
                    a[mf][3] = smu[(r + 8) * HS_STRIDE + pb + t + 4];
                }
                #pragma unroll
                for (int nf = 0; nf < 4; ++nf) {
                    int n = wn2 + nf * 8 + g;
                    uint32_t bb0 = w2p[n * 20 + pb2 + t];
                    uint32_t bb1 = w2p[n * 20 + pb2 + t + 4];
                    #pragma unroll
                    for (int mf = 0; mf < 4; ++mf)
                        mma_f16(acc2[mf][nf], a[mf], bb0, bb1);
                }
            }
            __syncthreads();
        }
        // all warps done reading Hs; next expert's stageA may overwrite it
    }

    // ===== epilogue: out = acc2 + sum_e w[b,e] * b2[e,:] =====
    #pragma unroll
    for (int mf = 0; mf < 4; ++mf) {
        int r0 = wm + mf * 16 + g, r1 = r0 + 8;
        #pragma unroll
        for (int nf = 0; nf < 4; ++nf) {
            int c0 = wn2 + nf * 8 + 2 * t;
            float s0 = acc2[mf][nf][0], s1 = acc2[mf][nf][1];
            float s2 = acc2[mf][nf][2], s3 = acc2[mf][nf][3];
            #pragma unroll
            for (int e = 0; e < NE; ++e) {
                float bb0 = b2[e * OUT + c0], bb1 = b2[e * OUT + c0 + 1];
                float we0 = wts[r0 * NE + e], we1 = wts[r1 * NE + e];
                s0 += we0 * bb0; s1 += we0 * bb1;
                s2 += we1 * bb0; s3 += we1 * bb1;
            }
            out[(size_t)(b0 + r0) * OUT + c0]     = s0;
            out[(size_t)(b0 + r0) * OUT + c0 + 1] = s1;
            out[(size_t)(b0 + r1) * OUT + c0]     = s2;
            out[(size_t)(b0 + r1) * OUT + c0 + 1] = s3;
        }
    }
}

// ---------------- launch (2 kernels) ----------------
extern "C" void kernel_launch(void* const* d_in, const int* in_sizes, int n_in,
                              void* d_out, int out_size) {
    const float* x  = (const float*)d_in[0];
    const float* u  = (const float*)d_in[1];
    const float* dd = (const float*)d_in[2];
    const float* gW = (const float*)d_in[3];
    const float* gb = (const float*)d_in[4];
    const float* W1 = (const float*)d_in[5];
    const float* b1 = (const float*)d_in[6];
    const float* W2 = (const float*)d_in[7];
    const float* b2 = (const float*)d_in[8];
    float* out = (float*)d_out;

    cudaFuncSetAttribute(gate_k, cudaFuncAttributeMaxDynamicSharedMemorySize,
                         GATE_IN * NE * 4);
    cudaFuncSetAttribute(moe_main, cudaFuncAttributeMaxDynamicSharedMemorySize,
                         SMEM_BYTES);

    gate_k<<<BB / 256, 256, GATE_IN * NE * 4>>>(u, x, dd, gW, gb, W1, W2);
    moe_main<<<BB / 128, 256, SMEM_BYTES>>>(b1, b2, out);
}

// round 10
// speedup vs baseline: 2.7018x; 1.6831x over previous
#include <cuda_runtime.h>
#include <cuda_fp16.h>
#include <cstdint>

#define BB 32768
#define IN 512
#define HID 256
#define OUT 128
#define NE 16
#define CTX 256
#define DEMO 16
#define GATE_IN 784

// ---------------- device scratch: fp16 pairs packed in u32 along K ----------------
__device__ uint32_t g_xh[BB * IN / 2];           // x  as fp16x2
__device__ uint32_t g_w1h[NE * HID * IN / 2];    // W1 as fp16x2
__device__ uint32_t g_w2h[NE * OUT * HID / 2];   // W2 as fp16x2
__device__ float    g_wgt[BB * NE];              // softmax gate weights

// ---------------- helpers ----------------
__device__ __forceinline__ uint32_t pack_h2(float a, float b) {
    __half2 h = __floats2half2_rn(a, b);
    return *(uint32_t*)&h;
}
__device__ __forceinline__ void cp16(void* s, const void* g) {
    uint32_t sa = (uint32_t)__cvta_generic_to_shared(s);
    asm volatile("cp.async.cg.shared.global [%0], [%1], 16;" :: "r"(sa), "l"(g));
}
__device__ __forceinline__ void cp_commit() { asm volatile("cp.async.commit_group;"); }
__device__ __forceinline__ void cp_wait0()  { asm volatile("cp.async.wait_group 0;" ::: "memory"); }
__device__ __forceinline__ void cp_wait1()  { asm volatile("cp.async.wait_group 1;" ::: "memory"); }

__device__ __forceinline__ void mma_f16(float* c, const uint32_t* a,
                                        uint32_t b0, uint32_t b1) {
    asm volatile(
        "mma.sync.aligned.m16n8k16.row.col.f32.f16.f16.f32 "
        "{%0,%1,%2,%3},{%4,%5,%6,%7},{%8,%9},{%0,%1,%2,%3};\n"
        : "+f"(c[0]), "+f"(c[1]), "+f"(c[2]), "+f"(c[3])
        : "r"(a[0]), "r"(a[1]), "r"(a[2]), "r"(a[3]), "r"(b0), "r"(b1));
}

// ---------------- gate: logits + softmax + fused x/W fp16 conversion ----------------
#define W1_F4 (NE * HID * IN / 4)
#define W2_F4 (NE * OUT * HID / 4)

__device__ __forceinline__ void gfma(float* acc, const float* gWs, int k, float v) {
    const float4* w = (const float4*)(gWs + k * 16);
    #pragma unroll
    for (int q = 0; q < 4; ++q) {
        float4 ww = w[q];
        acc[q * 4 + 0] += v * ww.x; acc[q * 4 + 1] += v * ww.y;
        acc[q * 4 + 2] += v * ww.z; acc[q * 4 + 3] += v * ww.w;
    }
}

__global__ __launch_bounds__(256) void gate_k(
    const float* __restrict__ u, const float* __restrict__ x,
    const float* __restrict__ d, const float* __restrict__ gW,
    const float* __restrict__ gb,
    const float* __restrict__ W1, const float* __restrict__ W2) {
    extern __shared__ float gWs[];  // [784][16] transposed
    int tid = threadIdx.x;

    {
        int gtid = blockIdx.x * 256 + tid;
        int nthr = gridDim.x * 256;
        for (int i = gtid; i < W1_F4; i += nthr) {
            float4 v = ((const float4*)W1)[i];
            g_w1h[2 * i]     = pack_h2(v.x, v.y);
            g_w1h[2 * i + 1] = pack_h2(v.z, v.w);
        }
        for (int i = gtid; i < W2_F4; i += nthr) {
            float4 v = ((const float4*)W2)[i];
            g_w2h[2 * i]     = pack_h2(v.x, v.y);
            g_w2h[2 * i + 1] = pack_h2(v.z, v.w);
        }
    }

    for (int i = tid; i < GATE_IN * NE; i += 256) {
        int e = i / GATE_IN, k = i - e * GATE_IN;
        gWs[k * 16 + e] = gW[i];
    }
    __syncthreads();

    int r = blockIdx.x * 256 + tid;
    float acc[16];
    #pragma unroll
    for (int e = 0; e < 16; ++e) acc[e] = gb[e];

    const float4* u4 = (const float4*)(u + (size_t)r * CTX);
    const float4* x4 = (const float4*)(x + (size_t)r * IN);
    const float4* d4 = (const float4*)(d + (size_t)r * DEMO);

    int kb = 0;
    #pragma unroll 4
    for (int i = 0; i < CTX / 4; ++i) {
        float4 v = u4[i];
        gfma(acc, gWs, kb + 0, v.x); gfma(acc, gWs, kb + 1, v.y);
        gfma(acc, gWs, kb + 2, v.z); gfma(acc, gWs, kb + 3, v.w);
        kb += 4;
    }
    #pragma unroll 4
    for (int i = 0; i < IN / 4; ++i) {
        float4 v = x4[i];
        gfma(acc, gWs, kb + 0, v.x); gfma(acc, gWs, kb + 1, v.y);
        gfma(acc, gWs, kb + 2, v.z); gfma(acc, gWs, kb + 3, v.w);
        kb += 4;
        size_t bidx = (size_t)r * (IN / 2) + 2 * i;
        g_xh[bidx]     = pack_h2(v.x, v.y);
        g_xh[bidx + 1] = pack_h2(v.z, v.w);
    }
    #pragma unroll
    for (int i = 0; i < DEMO / 4; ++i) {
        float4 v = d4[i];
        gfma(acc, gWs, kb + 0, v.x); gfma(acc, gWs, kb + 1, v.y);
        gfma(acc, gWs, kb + 2, v.z); gfma(acc, gWs, kb + 3, v.w);
        kb += 4;
    }

    float m = acc[0];
    #pragma unroll
    for (int e = 1; e < 16; ++e) m = fmaxf(m, acc[e]);
    float s = 0.f;
    #pragma unroll
    for (int e = 0; e < 16; ++e) { acc[e] = expf(acc[e] - m); s += acc[e]; }
    float inv = 1.f / s;
    #pragma unroll
    for (int e = 0; e < 16; ++e) g_wgt[(size_t)r * NE + e] = acc[e] * inv;
}

// ---------------- main fused MoE kernel (fp16, K=64 chunks, 3-stage pipeline) ----------------
// SMEM u32 layout (52736 u32 = 210944 B):
//   [0, 41472)       A staging: XA 3 x (128*36)=13824 at 0 ; WA 3 x (256*36)=27648 at 13824
//     Hs (128 x 132) aliases [0, 16896)  (live: epilogue A -> end of phase B)
//   [41472, 50688)   W2 staging: 2 x (128*36)
//   [50688, 52736)   wts (float) 128 x 16
#define XA_OFF  0
#define XA_BUF  4608
#define WA_OFF  13824
#define WA_BUF  9216
#define HS_STRIDE 132
#define W2_OFF  41472
#define W2_BUF  4608
#define WTS_OFF 50688
#define SMEM_BYTES (52736 * 4)

// K=64 chunk: 32 u32 (fp16-pairs) per row, row stride 36
__device__ __forceinline__ void stageA(uint32_t* sm, int tid, int b0, int e, int ci, int buf) {
    uint32_t* xs = sm + XA_OFF + buf * XA_BUF;
    uint32_t* ws = sm + WA_OFF + buf * WA_BUF;
    const uint32_t* xsrc = g_xh + (size_t)b0 * (IN / 2) + ci * 32;
    const uint32_t* wsrc = g_w1h + (size_t)e * HID * (IN / 2) + ci * 32;
    #pragma unroll
    for (int j = 0; j < 4; ++j) {               // X: 128 rows x 32 u32 (1024 cp16)
        int v = tid + j * 256;
        int r = v >> 3, q = (v & 7) * 4;
        cp16(xs + r * 36 + q, xsrc + (size_t)r * (IN / 2) + q);
    }
    #pragma unroll
    for (int j = 0; j < 8; ++j) {               // W1: 256 rows x 32 u32 (2048 cp16)
        int v = tid + j * 256;
        int n = v >> 3, q = (v & 7) * 4;
        cp16(ws + n * 36 + q, wsrc + (size_t)n * (IN / 2) + q);
    }
}
__device__ __forceinline__ void stageB(uint32_t* sm, int tid, int e, int ci, int buf) {
    uint32_t* w2 = sm + W2_OFF + buf * W2_BUF;
    const uint32_t* src = g_w2h + (size_t)e * OUT * (HID / 2) + ci * 32;
    #pragma unroll
    for (int j = 0; j < 4; ++j) {               // W2: 128 rows x 32 u32 (1024 cp16)
        int v = tid + j * 256;
        int o = v >> 3, q = (v & 7) * 4;
        cp16(w2 + o * 36 + q, src + (size_t)o * (HID / 2) + q);
    }
}

__global__ __launch_bounds__(256, 1) void moe_main(
    const float* __restrict__ b1, const float* __restrict__ b2,
    float* __restrict__ out) {
    extern __shared__ uint32_t smu[];
    const int tid  = threadIdx.x;
    const int warp = tid >> 5, lane = tid & 31;
    const int g = lane >> 2, t = lane & 3;
    const int b0 = blockIdx.x * 128;

    float* wts = (float*)(smu + WTS_OFF);
    for (int i = tid; i < 128 * NE; i += 256) wts[i] = g_wgt[(size_t)b0 * NE + i];

    // warp tiling: 2 (M) x 4 (N) warps
    const int wm  = (warp & 1) * 64;   // row base (both phases)
    const int wn1 = (warp >> 1) * 64;  // phase-A col base (HID=256)
    const int wn2 = (warp >> 1) * 32;  // phase-B col base (OUT=128)

    float acc2[4][4][4];               // persistent mixture accumulator
    #pragma unroll
    for (int a = 0; a < 4; ++a)
        #pragma unroll
        for (int b = 0; b < 4; ++b)
            #pragma unroll
            for (int c = 0; c < 4; ++c) acc2[a][b][c] = 0.f;

    __syncthreads();

    for (int e = 0; e < NE; ++e) {
        // ===== Phase A: H = relu(X @ W1_e^T + b1) * w  (K=512, 8 chunks of 64) =====
        float acc1[4][8][4];
        #pragma unroll
        for (int a = 0; a < 4; ++a)
            #pragma unroll
            for (int b = 0; b < 8; ++b)
                #pragma unroll
                for (int c = 0; c < 4; ++c) acc1[a][b][c] = 0.f;

        stageA(smu, tid, b0, e, 0, 0); cp_commit();
        stageA(smu, tid, b0, e, 1, 1); cp_commit();

        for (int ci = 0; ci < 8; ++ci) {
            if (ci < 7) cp_wait1(); else cp_wait0();  // oldest group (chunk ci) complete
            __syncthreads();                          // single sync: data visible + buffer(ci+2) free
            if (ci < 6) { stageA(smu, tid, b0, e, ci + 2, (ci + 2) % 3); cp_commit(); }
            const uint32_t* xp = smu + XA_OFF + (ci % 3) * XA_BUF;
            const uint32_t* wp = smu + WA_OFF + (ci % 3) * WA_BUF;
            #pragma unroll
            for (int ks = 0; ks < 4; ++ks) {          // four k16 slices per K=64 chunk
                const int pb = ks * 8;                // pair base
                uint32_t a[4][4];
                #pragma unroll
                for (int mf = 0; mf < 4; ++mf) {
                    int r = wm + mf * 16 + g;
                    a[mf][0] = xp[r * 36 + pb + t];
                    a[mf][1] = xp[(r + 8) * 36 + pb + t];
                    a[mf][2] = xp[r * 36 + pb + t + 4];
                    a[mf][3] = xp[(r + 8) * 36 + pb + t + 4];
                }
                #pragma unroll
                for (int nf = 0; nf < 8; ++nf) {
                    int n = wn1 + nf * 8 + g;
                    uint32_t bb0 = wp[n * 36 + pb + t];
                    uint32_t bb1 = wp[n * 36 + pb + t + 4];
                    #pragma unroll
                    for (int mf = 0; mf < 4; ++mf)
                        mma_f16(acc1[mf][nf], a[mf], bb0, bb1);
                }
            }
        }

        // prefetch W2 chunk0 (separate region; lands during epilogue)
        stageB(smu, tid, e, 0, 0); cp_commit();
        __syncthreads();   // all warps done reading A buffers before Hs (aliased) is written

        // epilogue A: relu + bias + gate-weight scale, fp16 pack, store H
        #pragma unroll
        for (int mf = 0; mf < 4; ++mf) {
            int r0 = wm + mf * 16 + g, r1 = r0 + 8;
            float w0 = wts[r0 * NE + e], w1 = wts[r1 * NE + e];
            #pragma unroll
            for (int nf = 0; nf < 8; ++nf) {
                int c0 = wn1 + nf * 8 + 2 * t;
                int p  = c0 >> 1;                     // pair index
                float bb0 = b1[e * HID + c0], bb1 = b1[e * HID + c0 + 1];
                float v00 = fmaxf(acc1[mf][nf][0] + bb0, 0.f) * w0;
                float v01 = fmaxf(acc1[mf][nf][1] + bb1, 0.f) * w0;
                float v10 = fmaxf(acc1[mf][nf][2] + bb0, 0.f) * w1;
                float v11 = fmaxf(acc1[mf][nf][3] + bb1, 0.f) * w1;
                smu[r0 * HS_STRIDE + p] = pack_h2(v00, v01);
                smu[r1 * HS_STRIDE + p] = pack_h2(v10, v11);
            }
        }

        // ===== Phase B: out += (w*H_e) @ W2_e^T  (K=256, 4 chunks of 64) =====
        for (int ci = 0; ci < 4; ++ci) {
            int cur = ci & 1;
            cp_wait0(); __syncthreads();   // W2[cur] ready; ci==0 also publishes Hs stores
            if (ci < 3) { stageB(smu, tid, e, ci + 1, cur ^ 1); cp_commit(); }
            const uint32_t* w2p = smu + W2_OFF + cur * W2_BUF;
            #pragma unroll
            for (int ks = 0; ks < 4; ++ks) {
                const int pb  = ci * 32 + ks * 8;     // pair base into Hs
                const int pb2 = ks * 8;               // within W2 tile
                uint32_t a[4][4];
                #pragma unroll
                for (int mf = 0; mf < 4; ++mf) {
                    int r = wm + mf * 16 + g;
                    a[mf][0] = smu[r * HS_STRIDE + pb + t];
                    a[mf][1] = smu[(r + 8) * HS_STRIDE + pb + t];
                    a[mf][2] = smu[r * HS_STRIDE + pb + t + 4];
                    a[mf][3] = smu[(r + 8) * HS_STRIDE + pb + t + 4];
                }
                #pragma unroll
                for (int nf = 0; nf < 4; ++nf) {
                    int n = wn2 + nf * 8 + g;
                    uint32_t bb0 = w2p[n * 36 + pb2 + t];
                    uint32_t bb1 = w2p[n * 36 + pb2 + t + 4];
                    #pragma unroll
                    for (int mf = 0; mf < 4; ++mf)
                        mma_f16(acc2[mf][nf], a[mf], bb0, bb1);
                }
            }
            __syncthreads();   // all warps done with buf cur (and Hs at ci==3) before reuse
        }
        // trailing sync of last B iteration guards Hs/A-buffer reuse by next expert
    }

    // ===== epilogue: out = acc2 + sum_e w[b,e] * b2[e,:] =====
    #pragma unroll
    for (int mf = 0; mf < 4; ++mf) {
        int r0 = wm + mf * 16 + g, r1 = r0 + 8;
        #pragma unroll
        for (int nf = 0; nf < 4; ++nf) {
            int c0 = wn2 + nf * 8 + 2 * t;
            float s0 = acc2[mf][nf][0], s1 = acc2[mf][nf][1];
            float s2 = acc2[mf][nf][2], s3 = acc2[mf][nf][3];
            #pragma unroll
            for (int e = 0; e < NE; ++e) {
                float bb0 = b2[e * OUT + c0], bb1 = b2[e * OUT + c0 + 1];
                float we0 = wts[r0 * NE + e], we1 = wts[r1 * NE + e];
                s0 += we0 * bb0; s1 += we0 * bb1;
                s2 += we1 * bb0; s3 += we1 * bb1;
            }
            out[(size_t)(b0 + r0) * OUT + c0]     = s0;
            out[(size_t)(b0 + r0) * OUT + c0 + 1] = s1;
            out[(size_t)(b0 + r1) * OUT + c0]     = s2;
            out[(size_t)(b0 + r1) * OUT + c0 + 1] = s3;
        }
    }
}

// ---------------- launch (2 kernels) ----------------
extern "C" void kernel_launch(void* const* d_in, const int* in_sizes, int n_in,
                              void* d_out, int out_size) {
    const float* x  = (const float*)d_in[0];
    const float* u  = (const float*)d_in[1];
    const float* dd = (const float*)d_in[2];
    const float* gW = (const float*)d_in[3];
    const float* gb = (const float*)d_in[4];
    const float* W1 = (const float*)d_in[5];
    const float* b1 = (const float*)d_in[6];
    const float* W2 = (const float*)d_in[7];
    const float* b2 = (const float*)d_in[8];
    float* out = (float*)d_out;

    cudaFuncSetAttribute(gate_k, cudaFuncAttributeMaxDynamicSharedMemorySize,
                         GATE_IN * NE * 4);
    cudaFuncSetAttribute(moe_main, cudaFuncAttributeMaxDynamicSharedMemorySize,
                         SMEM_BYTES);

    gate_k<<<BB / 256, 256, GATE_IN * NE * 4>>>(u, x, dd, gW, gb, W1, W2);
    moe_main<<<BB / 128, 256, SMEM_BYTES>>>(b1, b2, out);
}